// round 7
// baseline (speedup 1.0000x reference)
#include <cuda_runtime.h>
#include <cuda_fp16.h>

#define H 128
#define N_USER_MAX 100000
#define N_ITEM_MAX 50000

// Precomputed projections stored as fp16 (halves gather traffic).
__device__ __half g_p_user[(size_t)N_USER_MAX * H];
__device__ __half g_p_item[(size_t)N_ITEM_MAX * H];

// ---- Packed fp32 (FFMA2) helpers: 2x fp32 FMA per instruction, full precision.
__device__ __forceinline__ unsigned long long pack2(float lo, float hi) {
    unsigned long long r;
    asm("mov.b64 %0, {%1, %2};" : "=l"(r) : "f"(lo), "f"(hi));
    return r;
}
__device__ __forceinline__ void ffma2(unsigned long long& d,
                                      unsigned long long a,
                                      unsigned long long b) {
    asm("fma.rn.f32x2 %0, %1, %2, %0;" : "+l"(d) : "l"(a), "l"(b));
}
__device__ __forceinline__ float2 unpack2(unsigned long long v) {
    float2 f;
    asm("mov.b64 {%0, %1}, %2;" : "=f"(f.x), "=f"(f.y) : "l"(v));
    return f;
}

// ---------------------------------------------------------------------------
// Fused precompute: one launch covers both tables.
//   blocks [0, nb_user)             : p_user = z_user @ W1[:128] + b1
//   blocks [nb_user, nb_user+nb_it) : p_item = z_item @ W1[128:]
// Tile: 64 rows x 128 cols per 128-thread block; 8 rows x 4 col-pairs per
// thread, accumulated in packed f32x2 (FFMA2). Per kk: 32 FFMA2 (64 FMA) +
// 2 LDG.128 (W, L1-resident) + 8 pack movs (alu pipe, overlapped).
// smem: 64*(128+4)*4 = 33.8 KB (under the 48 KB static cap).
// ---------------------------------------------------------------------------
__global__ __launch_bounds__(128) void precompute_fused(
    const float* __restrict__ z_user, const float* __restrict__ z_item,
    const float* __restrict__ W1, const float* __restrict__ b1,
    int n_user, int n_item, int nb_user)
{
    __shared__ float sA[64][H + 4];

    const bool is_user = (int)blockIdx.x < nb_user;
    const float* Z;
    const float* W;
    __half* P;
    int nrows, row0;
    if (is_user) {
        Z = z_user; W = W1;          P = g_p_user; nrows = n_user;
        row0 = blockIdx.x * 64;
    } else {
        Z = z_item; W = W1 + H * H;  P = g_p_item; nrows = n_item;
        row0 = (blockIdx.x - nb_user) * 64;
    }
    int rows_here = nrows - row0;
    if (rows_here > 64) rows_here = 64;

    const int tid = threadIdx.x;

    // Stage A tile (coalesced float4): 64 rows x 32 float4
    for (int i = tid; i < rows_here * (H / 4); i += 128) {
        int r  = i >> 5;
        int c4 = i & 31;
        float4 v = reinterpret_cast<const float4*>(Z + (size_t)(row0 + r) * H)[c4];
        *reinterpret_cast<float4*>(&sA[r][c4 * 4]) = v;
    }
    __syncthreads();

    const int tx = tid & 15;   // cols [tx*8, tx*8+8) -> 4 packed col-pairs
    const int ty = tid >> 4;   // rows [ty*8, ty*8+8)

    unsigned long long acc2[8][4];
#pragma unroll
    for (int r = 0; r < 8; r++)
#pragma unroll
        for (int c = 0; c < 4; c++) acc2[r][c] = 0ull;   // pair of +0.0f

    const float* Wp = W + tx * 8;

    for (int k0 = 0; k0 < H; k0 += 4) {
        float4 a[8];
#pragma unroll
        for (int r = 0; r < 8; r++)
            a[r] = *reinterpret_cast<const float4*>(&sA[ty * 8 + r][k0]);
#pragma unroll
        for (int kk = 0; kk < 4; kk++) {
            float4 w0 = __ldg(reinterpret_cast<const float4*>(Wp + (size_t)(k0 + kk) * H));
            float4 w1 = __ldg(reinterpret_cast<const float4*>(Wp + (size_t)(k0 + kk) * H + 4));
            unsigned long long ww[4] = {
                pack2(w0.x, w0.y), pack2(w0.z, w0.w),
                pack2(w1.x, w1.y), pack2(w1.z, w1.w)
            };
#pragma unroll
            for (int r = 0; r < 8; r++) {
                float av = (kk == 0) ? a[r].x : (kk == 1) ? a[r].y
                         : (kk == 2) ? a[r].z : a[r].w;
                unsigned long long aa = pack2(av, av);
#pragma unroll
                for (int c = 0; c < 4; c++)
                    ffma2(acc2[r][c], aa, ww[c]);
            }
        }
    }

    // Bias (user table only), then convert col-pairs straight to half2, store.
    float2 bias2[4];
    if (is_user) {
#pragma unroll
        for (int j = 0; j < 4; j++) {
            bias2[j].x = __ldg(b1 + tx * 8 + 2 * j);
            bias2[j].y = __ldg(b1 + tx * 8 + 2 * j + 1);
        }
    }

#pragma unroll
    for (int r = 0; r < 8; r++) {
        int rr = ty * 8 + r;
        if (rr < rows_here) {
            __half2 h[4];
#pragma unroll
            for (int j = 0; j < 4; j++) {
                float2 p = unpack2(acc2[r][j]);
                if (is_user) { p.x += bias2[j].x; p.y += bias2[j].y; }
                h[j] = __floats2half2_rn(p.x, p.y);
            }
            *reinterpret_cast<uint4*>(P + (size_t)(row0 + rr) * H + tx * 8) =
                *reinterpret_cast<uint4*>(h);
        }
    }
}

// ---------------------------------------------------------------------------
// Edge kernel: 8 lanes per edge, 4 edges per warp-iteration, grid-stride.
//   out[e] = sum_c relu(pu[row[e]][c] + pi[col[e]][c]) * W2[c] + b2
// Each lane loads 2x uint4 (16 halves = 32 B) per table -> 256 B coalesced row.
// ---------------------------------------------------------------------------
__global__ __launch_bounds__(256) void edge_kernel(
    const int* __restrict__ row, const int* __restrict__ col,
    const float* __restrict__ W2, const float* __restrict__ b2,
    float* __restrict__ out, int E)
{
    const int lane = threadIdx.x & 31;
    const int sub  = lane >> 3;   // edge slot 0..3 within warp
    const int l    = lane & 7;    // lane within edge: halves [l*16, l*16+16)

    float w2v[16];
#pragma unroll
    for (int i = 0; i < 16; i++) w2v[i] = __ldg(W2 + l * 16 + i);
    const float b2v = __ldg(b2);

    const int warp_global = (int)((blockIdx.x * 256u + threadIdx.x) >> 5);
    const int total_warps = (int)((gridDim.x * 256u) >> 5);

    for (int e = warp_global * 4 + sub; e < E; e += total_warps * 4) {
        const int u = __ldg(row + e);
        const int v = __ldg(col + e);

        const uint4* pu = reinterpret_cast<const uint4*>(g_p_user + (size_t)u * H) + l * 2;
        const uint4* pi = reinterpret_cast<const uint4*>(g_p_item + (size_t)v * H) + l * 2;
        uint4 a0 = pu[0];
        uint4 a1 = pu[1];
        uint4 c0 = pi[0];
        uint4 c1 = pi[1];

        const __half2* A0 = reinterpret_cast<const __half2*>(&a0);
        const __half2* A1 = reinterpret_cast<const __half2*>(&a1);
        const __half2* C0 = reinterpret_cast<const __half2*>(&c0);
        const __half2* C1 = reinterpret_cast<const __half2*>(&c1);

        float s = 0.f;
#pragma unroll
        for (int j = 0; j < 4; j++) {
            float2 fa = __half22float2(A0[j]);
            float2 fb = __half22float2(C0[j]);
            s = fmaf(fmaxf(fa.x + fb.x, 0.f), w2v[2 * j],     s);
            s = fmaf(fmaxf(fa.y + fb.y, 0.f), w2v[2 * j + 1], s);
        }
#pragma unroll
        for (int j = 0; j < 4; j++) {
            float2 fa = __half22float2(A1[j]);
            float2 fb = __half22float2(C1[j]);
            s = fmaf(fmaxf(fa.x + fb.x, 0.f), w2v[8 + 2 * j],     s);
            s = fmaf(fmaxf(fa.y + fb.y, 0.f), w2v[8 + 2 * j + 1], s);
        }

#pragma unroll
        for (int off = 4; off; off >>= 1)
            s += __shfl_xor_sync(0xFFFFFFFFu, s, off);

        if (l == 0) out[e] = s + b2v;
    }
}

// ---------------------------------------------------------------------------
// Inputs (metadata order): z_user f32[100000*128], z_item f32[50000*128],
//   row i32[E], col i32[E], W1 f32[256*128], b1 f32[128], W2 f32[128], b2 f32[1]
// Output: f32[E]
// ---------------------------------------------------------------------------
extern "C" void kernel_launch(void* const* d_in, const int* in_sizes, int n_in,
                              void* d_out, int out_size)
{
    const float* z_user = (const float*)d_in[0];
    const float* z_item = (const float*)d_in[1];
    const int*   row    = (const int*)d_in[2];
    const int*   col    = (const int*)d_in[3];
    const float* W1     = (const float*)d_in[4];
    const float* b1     = (const float*)d_in[5];
    const float* W2     = (const float*)d_in[6];
    const float* b2     = (const float*)d_in[7];
    float* out = (float*)d_out;

    const int n_user = in_sizes[0] / H;
    const int n_item = in_sizes[1] / H;
    const int E      = in_sizes[2];

    const int nb_user = (n_user + 63) / 64;
    const int nb_item = (n_item + 63) / 64;

    precompute_fused<<<nb_user + nb_item, 128>>>(z_user, z_item, W1, b1,
                                                 n_user, n_item, nb_user);

    edge_kernel<<<1184, 256>>>(row, col, W2, b2, out, E);
}

// round 8
// speedup vs baseline: 1.5729x; 1.5729x over previous
#include <cuda_runtime.h>
#include <cuda_fp16.h>
#include <cstdint>

#define H 128
#define N_USER_MAX 100000
#define N_ITEM_MAX 50000

// Precomputed projections stored as fp16 (halves edge gather traffic).
__device__ __half g_p_user[(size_t)N_USER_MAX * H];
__device__ __half g_p_item[(size_t)N_ITEM_MAX * H];

// W1 pre-packed into tf32 mma B-fragments.
// Layout: [table(2)][kstep(16)][tpair(8)][lane(32)] float4 =
//   (b0 of coltile 2*tp, b1 of 2*tp, b0 of 2*tp+1, b1 of 2*tp+1)
// where for coltile t, lane l: b0 = W[(8s + l%4)*H + 8t + l/4], b1 = same k+4.
__device__ float4 g_wfrag[2 * 16 * 8 * 32];

__device__ __forceinline__ uint32_t f2tf32(float x) {
    uint32_t r;
    asm("cvt.rna.tf32.f32 %0, %1;" : "=r"(r) : "f"(x));
    return r;
}

#define MMA_TF32(d, A0, A1, A2, A3, B0, B1)                                  \
    asm volatile(                                                            \
        "mma.sync.aligned.m16n8k8.row.col.f32.tf32.tf32.f32 "                \
        "{%0,%1,%2,%3}, {%4,%5,%6,%7}, {%8,%9}, {%0,%1,%2,%3};"              \
        : "+f"(d[0]), "+f"(d[1]), "+f"(d[2]), "+f"(d[3])                     \
        : "r"(A0), "r"(A1), "r"(A2), "r"(A3), "r"(B0), "r"(B1))

// ---------------------------------------------------------------------------
// convert_w: pack W1 (2H x H, fp32) into tf32 B-fragment layout. 8192 threads.
// ---------------------------------------------------------------------------
__global__ __launch_bounds__(256) void convert_w(const float* __restrict__ W1)
{
    int idx = blockIdx.x * 256 + threadIdx.x;   // 0..8191
    int lane = idx & 31;
    int tp   = (idx >> 5) & 7;
    int s    = (idx >> 8) & 15;
    int tb   = idx >> 12;

    const float* Wb = W1 + tb * H * H;
    int k0 = 8 * s + (lane & 3);
    int n  = lane >> 2;
    int c0 = 16 * tp + n;       // coltile 2*tp
    int c1 = 16 * tp + 8 + n;   // coltile 2*tp+1

    float4 o;
    o.x = __uint_as_float(f2tf32(Wb[(size_t)k0 * H + c0]));
    o.y = __uint_as_float(f2tf32(Wb[(size_t)(k0 + 4) * H + c0]));
    o.z = __uint_as_float(f2tf32(Wb[(size_t)k0 * H + c1]));
    o.w = __uint_as_float(f2tf32(Wb[(size_t)(k0 + 4) * H + c1]));
    g_wfrag[idx] = o;
}

// ---------------------------------------------------------------------------
// Precompute via tf32 warp-mma. One warp = one 16-row tile x all 128 cols.
// Block = 256 threads = 8 warps = 128 rows. No smem, no __syncthreads.
// Per k-step: 4 LDG.32 + 4 cvt (A), 8 LDG.128 (B pairs), 16 mma.
// fp32 accumulate; bias (user table) added fp32; stored fp16.
// ---------------------------------------------------------------------------
__global__ __launch_bounds__(256) void precompute_mma(
    const float* __restrict__ z_user, const float* __restrict__ z_item,
    const float* __restrict__ b1,
    int n_user, int n_item, int nb_user)
{
    const int warp = threadIdx.x >> 5;
    const int lane = threadIdx.x & 31;

    const bool is_user = (int)blockIdx.x < nb_user;
    const float* Z;
    __half* P;
    int nrows, tb, blk;
    if (is_user) { Z = z_user; P = g_p_user; nrows = n_user; tb = 0; blk = blockIdx.x; }
    else         { Z = z_item; P = g_p_item; nrows = n_item; tb = 1; blk = blockIdx.x - nb_user; }

    const int row0 = blk * 128 + warp * 16;
    if (row0 >= nrows) return;   // warp-uniform, no barriers in kernel

    const int r_lo = row0 + (lane >> 2);
    const int r_hi = r_lo + 8;
    const int r_lo_c = (r_lo < nrows) ? r_lo : (nrows - 1);
    const int r_hi_c = (r_hi < nrows) ? r_hi : (nrows - 1);

    const float* zlo = Z + (size_t)r_lo_c * H + (lane & 3);
    const float* zhi = Z + (size_t)r_hi_c * H + (lane & 3);
    const float4* wf = g_wfrag + (size_t)tb * 16 * 8 * 32 + lane;

    float acc[16][4];
#pragma unroll
    for (int t = 0; t < 16; t++)
#pragma unroll
        for (int c = 0; c < 4; c++) acc[t][c] = 0.f;

#pragma unroll
    for (int s = 0; s < 16; s++) {
        uint32_t a0 = f2tf32(__ldg(zlo + 8 * s));
        uint32_t a2 = f2tf32(__ldg(zlo + 8 * s + 4));
        uint32_t a1 = f2tf32(__ldg(zhi + 8 * s));
        uint32_t a3 = f2tf32(__ldg(zhi + 8 * s + 4));
        const float4* wfs = wf + (size_t)s * 8 * 32;
#pragma unroll
        for (int tp = 0; tp < 8; tp++) {
            float4 b = __ldg(wfs + (size_t)tp * 32);
            uint32_t b0a = __float_as_uint(b.x);
            uint32_t b1a = __float_as_uint(b.y);
            uint32_t b0b = __float_as_uint(b.z);
            uint32_t b1b = __float_as_uint(b.w);
            MMA_TF32(acc[2 * tp],     a0, a1, a2, a3, b0a, b1a);
            MMA_TF32(acc[2 * tp + 1], a0, a1, a2, a3, b0b, b1b);
        }
    }

    // Epilogue: bias (user only, fp32) + fp16 store.
    const int colm = 2 * (lane & 3);
#pragma unroll
    for (int t = 0; t < 16; t++) {
        float c0 = acc[t][0], c1 = acc[t][1], c2 = acc[t][2], c3 = acc[t][3];
        if (is_user) {
            float2 bb = *reinterpret_cast<const float2*>(b1 + 8 * t + colm);
            c0 += bb.x; c1 += bb.y; c2 += bb.x; c3 += bb.y;
        }
        __half2 h01 = __floats2half2_rn(c0, c1);
        __half2 h23 = __floats2half2_rn(c2, c3);
        if (r_lo < nrows)
            *reinterpret_cast<__half2*>(P + (size_t)r_lo * H + 8 * t + colm) = h01;
        if (r_hi < nrows)
            *reinterpret_cast<__half2*>(P + (size_t)r_hi * H + 8 * t + colm) = h23;
    }
}

// ---------------------------------------------------------------------------
// Edge kernel: 8 lanes per edge, 4 edges per warp-iteration, grid-stride.
//   out[e] = sum_c relu(pu[row[e]][c] + pi[col[e]][c]) * W2[c] + b2
// ---------------------------------------------------------------------------
__global__ __launch_bounds__(256) void edge_kernel(
    const int* __restrict__ row, const int* __restrict__ col,
    const float* __restrict__ W2, const float* __restrict__ b2,
    float* __restrict__ out, int E)
{
    const int lane = threadIdx.x & 31;
    const int sub  = lane >> 3;
    const int l    = lane & 7;

    float w2v[16];
#pragma unroll
    for (int i = 0; i < 16; i++) w2v[i] = __ldg(W2 + l * 16 + i);
    const float b2v = __ldg(b2);

    const int warp_global = (int)((blockIdx.x * 256u + threadIdx.x) >> 5);
    const int total_warps = (int)((gridDim.x * 256u) >> 5);

    for (int e = warp_global * 4 + sub; e < E; e += total_warps * 4) {
        const int u = __ldg(row + e);
        const int v = __ldg(col + e);

        const uint4* pu = reinterpret_cast<const uint4*>(g_p_user + (size_t)u * H) + l * 2;
        const uint4* pi = reinterpret_cast<const uint4*>(g_p_item + (size_t)v * H) + l * 2;
        uint4 a0 = pu[0];
        uint4 a1 = pu[1];
        uint4 c0 = pi[0];
        uint4 c1 = pi[1];

        const __half2* A0 = reinterpret_cast<const __half2*>(&a0);
        const __half2* A1 = reinterpret_cast<const __half2*>(&a1);
        const __half2* C0 = reinterpret_cast<const __half2*>(&c0);
        const __half2* C1 = reinterpret_cast<const __half2*>(&c1);

        float s = 0.f;
#pragma unroll
        for (int j = 0; j < 4; j++) {
            float2 fa = __half22float2(A0[j]);
            float2 fb = __half22float2(C0[j]);
            s = fmaf(fmaxf(fa.x + fb.x, 0.f), w2v[2 * j],     s);
            s = fmaf(fmaxf(fa.y + fb.y, 0.f), w2v[2 * j + 1], s);
        }
#pragma unroll
        for (int j = 0; j < 4; j++) {
            float2 fa = __half22float2(A1[j]);
            float2 fb = __half22float2(C1[j]);
            s = fmaf(fmaxf(fa.x + fb.x, 0.f), w2v[8 + 2 * j],     s);
            s = fmaf(fmaxf(fa.y + fb.y, 0.f), w2v[8 + 2 * j + 1], s);
        }

#pragma unroll
        for (int off = 4; off; off >>= 1)
            s += __shfl_xor_sync(0xFFFFFFFFu, s, off);

        if (l == 0) out[e] = s + b2v;
    }
}

// ---------------------------------------------------------------------------
// Inputs (metadata order): z_user f32[100000*128], z_item f32[50000*128],
//   row i32[E], col i32[E], W1 f32[256*128], b1 f32[128], W2 f32[128], b2 f32[1]
// Output: f32[E]
// ---------------------------------------------------------------------------
extern "C" void kernel_launch(void* const* d_in, const int* in_sizes, int n_in,
                              void* d_out, int out_size)
{
    const float* z_user = (const float*)d_in[0];
    const float* z_item = (const float*)d_in[1];
    const int*   row    = (const int*)d_in[2];
    const int*   col    = (const int*)d_in[3];
    const float* W1     = (const float*)d_in[4];
    const float* b1     = (const float*)d_in[5];
    const float* W2     = (const float*)d_in[6];
    const float* b2     = (const float*)d_in[7];
    float* out = (float*)d_out;

    const int n_user = in_sizes[0] / H;
    const int n_item = in_sizes[1] / H;
    const int E      = in_sizes[2];

    const int nb_user = (n_user + 127) / 128;
    const int nb_item = (n_item + 127) / 128;

    convert_w<<<32, 256>>>(W1);
    precompute_mma<<<nb_user + nb_item, 256>>>(z_user, z_item, b1,
                                               n_user, n_item, nb_user);
    edge_kernel<<<1184, 256>>>(row, col, W2, b2, out, E);
}

// round 9
// speedup vs baseline: 1.8671x; 1.1870x over previous
#include <cuda_runtime.h>
#include <cuda_fp16.h>
#include <cstdint>

#define H 128
#define N_USER_MAX 100000
#define N_ITEM_MAX 50000

// Precomputed projections stored as fp16 (halves edge gather traffic).
__device__ __half g_p_user[(size_t)N_USER_MAX * H];
__device__ __half g_p_item[(size_t)N_ITEM_MAX * H];

// W1 pre-packed into tf32 mma B-fragments.
// Layout: [table(2)][kstep(16)][tpair(8)][lane(32)] float4 =
//   (b0 of coltile 2*tp, b1 of 2*tp, b0 of 2*tp+1, b1 of 2*tp+1)
__device__ float4 g_wfrag[2 * 16 * 8 * 32];

__device__ __forceinline__ uint32_t f2tf32(float x) {
    uint32_t r;
    asm("cvt.rna.tf32.f32 %0, %1;" : "=r"(r) : "f"(x));
    return r;
}

#define MMA_TF32(d, A0, A1, A2, A3, B0, B1)                                  \
    asm volatile(                                                            \
        "mma.sync.aligned.m16n8k8.row.col.f32.tf32.tf32.f32 "                \
        "{%0,%1,%2,%3}, {%4,%5,%6,%7}, {%8,%9}, {%0,%1,%2,%3};"              \
        : "+f"(d[0]), "+f"(d[1]), "+f"(d[2]), "+f"(d[3])                     \
        : "r"(A0), "r"(A1), "r"(A2), "r"(A3), "r"(B0), "r"(B1))

// ---------------------------------------------------------------------------
// convert_w: pack W1 (2H x H, fp32) into tf32 B-fragment layout. 8192 threads.
// ---------------------------------------------------------------------------
__global__ __launch_bounds__(256) void convert_w(const float* __restrict__ W1)
{
    int idx = blockIdx.x * 256 + threadIdx.x;   // 0..8191
    int lane = idx & 31;
    int tp   = (idx >> 5) & 7;
    int s    = (idx >> 8) & 15;
    int tb   = idx >> 12;

    const float* Wb = W1 + tb * H * H;
    int k0 = 8 * s + (lane & 3);
    int n  = lane >> 2;
    int c0 = 16 * tp + n;
    int c1 = 16 * tp + 8 + n;

    float4 o;
    o.x = __uint_as_float(f2tf32(Wb[(size_t)k0 * H + c0]));
    o.y = __uint_as_float(f2tf32(Wb[(size_t)(k0 + 4) * H + c0]));
    o.z = __uint_as_float(f2tf32(Wb[(size_t)k0 * H + c1]));
    o.w = __uint_as_float(f2tf32(Wb[(size_t)(k0 + 4) * H + c1]));
    g_wfrag[idx] = o;
}

// ---------------------------------------------------------------------------
// Precompute via tf32 warp-mma. One warp = 32 rows x all 128 cols (two 16-row
// mma tiles share every B fragment -> W traffic halved vs 16-row warps).
// Block = 64 threads (2 warps); smem 2*32*132*4 = 33.8 KB (static cap OK).
// Fully warp-synchronous: no __syncthreads, warp-uniform early exit is safe.
// A-frags via conflict-free LDS.32 (stride 132 -> banks 4r+c distinct).
// Epilogue: fp16 via warp-private smem round-trip -> coalesced STG.128.
// ---------------------------------------------------------------------------
__global__ __launch_bounds__(64) void precompute_mma(
    const float* __restrict__ z_user, const float* __restrict__ z_item,
    const float* __restrict__ b1,
    int n_user, int n_item, int nb_user)
{
    __shared__ float sA[2][32][132];

    const int warp = threadIdx.x >> 5;
    const int lane = threadIdx.x & 31;

    const bool is_user = (int)blockIdx.x < nb_user;
    const float* Z;
    __half* P;
    int nrows, tb, blk;
    if (is_user) { Z = z_user; P = g_p_user; nrows = n_user; tb = 0; blk = blockIdx.x; }
    else         { Z = z_item; P = g_p_item; nrows = n_item; tb = 1; blk = blockIdx.x - nb_user; }

    const int row0 = blk * 64 + warp * 32;
    if (row0 >= nrows) return;   // warp-uniform

    float (*sa)[132] = sA[warp];

    // Stage this warp's 32 rows: 1 LDG.128 + 1 STS.128 per row (coalesced).
#pragma unroll 8
    for (int r = 0; r < 32; r++) {
        int rr = row0 + r;
        if (rr >= nrows) rr = nrows - 1;
        float4 v = __ldg(reinterpret_cast<const float4*>(Z + (size_t)rr * H) + lane);
        *reinterpret_cast<float4*>(&sa[r][lane * 4]) = v;
    }
    __syncwarp();

    const int qr = lane >> 2;   // 0..7 row within 8-row group
    const int qc = lane & 3;    // 0..3 col within k quad

    float acc[2][16][4];
#pragma unroll
    for (int rt = 0; rt < 2; rt++)
#pragma unroll
        for (int t = 0; t < 16; t++)
#pragma unroll
            for (int c = 0; c < 4; c++) acc[rt][t][c] = 0.f;

    const float4* wf = g_wfrag + (size_t)tb * 16 * 8 * 32 + lane;

#pragma unroll
    for (int s = 0; s < 16; s++) {
        // B fragments for this k-step: 8 float4 = 16 coltiles (MLP batch)
        float4 b[8];
        const float4* wfs = wf + (size_t)s * 8 * 32;
#pragma unroll
        for (int tp = 0; tp < 8; tp++) b[tp] = __ldg(wfs + (size_t)tp * 32);

        // A fragments for both 16-row tiles (conflict-free LDS.32)
        uint32_t a[2][4];
#pragma unroll
        for (int rt = 0; rt < 2; rt++) {
            int rb = rt * 16 + qr;
            a[rt][0] = f2tf32(sa[rb    ][8 * s + qc]);
            a[rt][1] = f2tf32(sa[rb + 8][8 * s + qc]);
            a[rt][2] = f2tf32(sa[rb    ][8 * s + 4 + qc]);
            a[rt][3] = f2tf32(sa[rb + 8][8 * s + 4 + qc]);
        }

#pragma unroll
        for (int tp = 0; tp < 8; tp++) {
            uint32_t b0a = __float_as_uint(b[tp].x);
            uint32_t b1a = __float_as_uint(b[tp].y);
            uint32_t b0b = __float_as_uint(b[tp].z);
            uint32_t b1b = __float_as_uint(b[tp].w);
#pragma unroll
            for (int rt = 0; rt < 2; rt++) {
                MMA_TF32(acc[rt][2 * tp],     a[rt][0], a[rt][1], a[rt][2], a[rt][3], b0a, b1a);
                MMA_TF32(acc[rt][2 * tp + 1], a[rt][0], a[rt][1], a[rt][2], a[rt][3], b0b, b1b);
            }
        }
    }

    // Epilogue: bias (user only) -> fp16 -> warp-private smem (conflict-free
    // half2 STS) -> coalesced LDS.128 + STG.128.
    __syncwarp();
    char* se = reinterpret_cast<char*>(sa);   // row r at byte r*528

#pragma unroll
    for (int t = 0; t < 16; t++) {
        float bx = 0.f, by = 0.f;
        if (is_user) {
            float2 bb = *reinterpret_cast<const float2*>(b1 + 8 * t + 2 * qc);
            bx = bb.x; by = bb.y;
        }
        int cb = (8 * t + 2 * qc) * 2;   // byte offset of half2 in row
#pragma unroll
        for (int rt = 0; rt < 2; rt++) {
            __half2 hlo = __floats2half2_rn(acc[rt][t][0] + bx, acc[rt][t][1] + by);
            __half2 hhi = __floats2half2_rn(acc[rt][t][2] + bx, acc[rt][t][3] + by);
            int rlo = rt * 16 + qr;
            *reinterpret_cast<__half2*>(se + (size_t)rlo * 528 + cb) = hlo;
            *reinterpret_cast<__half2*>(se + (size_t)(rlo + 8) * 528 + cb) = hhi;
        }
    }
    __syncwarp();

    // Write out: 2 rows per instruction, 512 B fully-coalesced.
    const int rl = lane >> 4;          // 0..1
    const int cl = lane & 15;          // 16 B chunk within 256 B row
#pragma unroll
    for (int i = 0; i < 16; i++) {
        int r  = 2 * i + rl;
        int gr = row0 + r;
        uint4 v = *reinterpret_cast<uint4*>(se + (size_t)r * 528 + cl * 16);
        if (gr < nrows)
            *reinterpret_cast<uint4*>(P + (size_t)gr * H + cl * 8) = v;
    }
}

// ---------------------------------------------------------------------------
// Edge kernel: 8 lanes per edge, 8 edges per warp-iteration (2x unroll for
// MLP: 8 gather LDG.128 in flight). Grid-stride.
// ---------------------------------------------------------------------------
__global__ __launch_bounds__(256) void edge_kernel(
    const int* __restrict__ row, const int* __restrict__ col,
    const float* __restrict__ W2, const float* __restrict__ b2,
    float* __restrict__ out, int E)
{
    const int lane = threadIdx.x & 31;
    const int sub  = lane >> 3;   // 0..3
    const int l    = lane & 7;    // lane within edge

    float w2v[16];
#pragma unroll
    for (int i = 0; i < 16; i++) w2v[i] = __ldg(W2 + l * 16 + i);
    const float b2v = __ldg(b2);

    const int warp_global = (int)((blockIdx.x * 256u + threadIdx.x) >> 5);
    const int total_warps = (int)((gridDim.x * 256u) >> 5);

    for (int eb = warp_global * 8; eb < E; eb += total_warps * 8) {
        int e0 = eb + sub;
        int e1 = eb + sub + 4;
        int e0c = (e0 < E) ? e0 : (E - 1);
        int e1c = (e1 < E) ? e1 : (E - 1);

        const int u0 = __ldg(row + e0c);
        const int v0 = __ldg(col + e0c);
        const int u1 = __ldg(row + e1c);
        const int v1 = __ldg(col + e1c);

        const uint4* pu0 = reinterpret_cast<const uint4*>(g_p_user + (size_t)u0 * H) + l * 2;
        const uint4* pi0 = reinterpret_cast<const uint4*>(g_p_item + (size_t)v0 * H) + l * 2;
        const uint4* pu1 = reinterpret_cast<const uint4*>(g_p_user + (size_t)u1 * H) + l * 2;
        const uint4* pi1 = reinterpret_cast<const uint4*>(g_p_item + (size_t)v1 * H) + l * 2;

        uint4 A0 = pu0[0], A1 = pu0[1];
        uint4 C0 = pi0[0], C1 = pi0[1];
        uint4 B0 = pu1[0], B1 = pu1[1];
        uint4 D0 = pi1[0], D1 = pi1[1];

        float s0 = 0.f, s1 = 0.f;
        const __half2* a0 = reinterpret_cast<const __half2*>(&A0);
        const __half2* a1 = reinterpret_cast<const __half2*>(&A1);
        const __half2* c0 = reinterpret_cast<const __half2*>(&C0);
        const __half2* c1 = reinterpret_cast<const __half2*>(&C1);
        const __half2* bb0 = reinterpret_cast<const __half2*>(&B0);
        const __half2* bb1 = reinterpret_cast<const __half2*>(&B1);
        const __half2* d0 = reinterpret_cast<const __half2*>(&D0);
        const __half2* d1 = reinterpret_cast<const __half2*>(&D1);

#pragma unroll
        for (int j = 0; j < 4; j++) {
            float2 fa = __half22float2(a0[j]);
            float2 fb = __half22float2(c0[j]);
            s0 = fmaf(fmaxf(fa.x + fb.x, 0.f), w2v[2 * j],     s0);
            s0 = fmaf(fmaxf(fa.y + fb.y, 0.f), w2v[2 * j + 1], s0);
            float2 ga = __half22float2(bb0[j]);
            float2 gb = __half22float2(d0[j]);
            s1 = fmaf(fmaxf(ga.x + gb.x, 0.f), w2v[2 * j],     s1);
            s1 = fmaf(fmaxf(ga.y + gb.y, 0.f), w2v[2 * j + 1], s1);
        }
#pragma unroll
        for (int j = 0; j < 4; j++) {
            float2 fa = __half22float2(a1[j]);
            float2 fb = __half22float2(c1[j]);
            s0 = fmaf(fmaxf(fa.x + fb.x, 0.f), w2v[8 + 2 * j],     s0);
            s0 = fmaf(fmaxf(fa.y + fb.y, 0.f), w2v[8 + 2 * j + 1], s0);
            float2 ga = __half22float2(bb1[j]);
            float2 gb = __half22float2(d1[j]);
            s1 = fmaf(fmaxf(ga.x + gb.x, 0.f), w2v[8 + 2 * j],     s1);
            s1 = fmaf(fmaxf(ga.y + gb.y, 0.f), w2v[8 + 2 * j + 1], s1);
        }

#pragma unroll
        for (int off = 4; off; off >>= 1) {
            s0 += __shfl_xor_sync(0xFFFFFFFFu, s0, off);
            s1 += __shfl_xor_sync(0xFFFFFFFFu, s1, off);
        }

        if (l == 0) {
            if (e0 < E) out[e0] = s0 + b2v;
            if (e1 < E) out[e1] = s1 + b2v;
        }
    }
}

// ---------------------------------------------------------------------------
// Inputs (metadata order): z_user f32[100000*128], z_item f32[50000*128],
//   row i32[E], col i32[E], W1 f32[256*128], b1 f32[128], W2 f32[128], b2 f32[1]
// Output: f32[E]
// ---------------------------------------------------------------------------
extern "C" void kernel_launch(void* const* d_in, const int* in_sizes, int n_in,
                              void* d_out, int out_size)
{
    const float* z_user = (const float*)d_in[0];
    const float* z_item = (const float*)d_in[1];
    const int*   row    = (const int*)d_in[2];
    const int*   col    = (const int*)d_in[3];
    const float* W1     = (const float*)d_in[4];
    const float* b1     = (const float*)d_in[5];
    const float* W2     = (const float*)d_in[6];
    const float* b2     = (const float*)d_in[7];
    float* out = (float*)d_out;

    const int n_user = in_sizes[0] / H;
    const int n_item = in_sizes[1] / H;
    const int E      = in_sizes[2];

    const int nb_user = (n_user + 63) / 64;
    const int nb_item = (n_item + 63) / 64;

    convert_w<<<32, 256>>>(W1);
    precompute_mma<<<nb_user + nb_item, 64>>>(z_user, z_item, b1,
                                              n_user, n_item, nb_user);
    edge_kernel<<<1184, 256>>>(row, col, W2, b2, out, E);
}

// round 10
// speedup vs baseline: 1.8677x; 1.0003x over previous
#include <cuda_runtime.h>
#include <cuda_fp16.h>
#include <cstdint>

#define H 128
#define N_USER_MAX 100000
#define N_ITEM_MAX 50000

// Precomputed projections stored as fp16 (halves edge gather traffic).
__device__ __half g_p_user[(size_t)N_USER_MAX * H];
__device__ __half g_p_item[(size_t)N_ITEM_MAX * H];

// W1 pre-packed into tf32 mma B-fragments.
// Layout: [table(2)][kstep(16)][tpair(8)][lane(32)] float4 =
//   (b0 of coltile 2*tp, b1 of 2*tp, b0 of 2*tp+1, b1 of 2*tp+1)
__device__ float4 g_wfrag[2 * 16 * 8 * 32];

__device__ __forceinline__ uint32_t f2tf32(float x) {
    uint32_t r;
    asm("cvt.rna.tf32.f32 %0, %1;" : "=r"(r) : "f"(x));
    return r;
}

#define MMA_TF32(d, A0, A1, A2, A3, B0, B1)                                  \
    asm volatile(                                                            \
        "mma.sync.aligned.m16n8k8.row.col.f32.tf32.tf32.f32 "                \
        "{%0,%1,%2,%3}, {%4,%5,%6,%7}, {%8,%9}, {%0,%1,%2,%3};"              \
        : "+f"(d[0]), "+f"(d[1]), "+f"(d[2]), "+f"(d[3])                     \
        : "r"(A0), "r"(A1), "r"(A2), "r"(A3), "r"(B0), "r"(B1))

// ---------------------------------------------------------------------------
// convert_w: pack W1 (2H x H, fp32) into tf32 B-fragment layout. 8192 threads.
// ---------------------------------------------------------------------------
__global__ __launch_bounds__(256) void convert_w(const float* __restrict__ W1)
{
    int idx = blockIdx.x * 256 + threadIdx.x;   // 0..8191
    int lane = idx & 31;
    int tp   = (idx >> 5) & 7;
    int s    = (idx >> 8) & 15;
    int tb   = idx >> 12;

    const float* Wb = W1 + tb * H * H;
    int k0 = 8 * s + (lane & 3);
    int n  = lane >> 2;
    int c0 = 16 * tp + n;
    int c1 = 16 * tp + 8 + n;

    float4 o;
    o.x = __uint_as_float(f2tf32(Wb[(size_t)k0 * H + c0]));
    o.y = __uint_as_float(f2tf32(Wb[(size_t)(k0 + 4) * H + c0]));
    o.z = __uint_as_float(f2tf32(Wb[(size_t)k0 * H + c1]));
    o.w = __uint_as_float(f2tf32(Wb[(size_t)(k0 + 4) * H + c1]));
    g_wfrag[idx] = o;
}

// ---------------------------------------------------------------------------
// Precompute via tf32 warp-mma. One warp = 32 rows x all 128 cols (two 16-row
// mma tiles share every B fragment -> W traffic halved vs 16-row warps).
// Block = 64 threads (2 warps); smem 2*32*132*4 = 33.8 KB (static cap OK).
// Fully warp-synchronous: no __syncthreads, warp-uniform early exit is safe.
// A-frags via conflict-free LDS.32 (stride 132 -> banks 4r+c distinct).
// Epilogue: fp16 via warp-private smem round-trip -> coalesced STG.128.
// ---------------------------------------------------------------------------
__global__ __launch_bounds__(64) void precompute_mma(
    const float* __restrict__ z_user, const float* __restrict__ z_item,
    const float* __restrict__ b1,
    int n_user, int n_item, int nb_user)
{
    __shared__ float sA[2][32][132];

    const int warp = threadIdx.x >> 5;
    const int lane = threadIdx.x & 31;

    const bool is_user = (int)blockIdx.x < nb_user;
    const float* Z;
    __half* P;
    int nrows, tb, blk;
    if (is_user) { Z = z_user; P = g_p_user; nrows = n_user; tb = 0; blk = blockIdx.x; }
    else         { Z = z_item; P = g_p_item; nrows = n_item; tb = 1; blk = blockIdx.x - nb_user; }

    const int row0 = blk * 64 + warp * 32;
    if (row0 >= nrows) return;   // warp-uniform

    float (*sa)[132] = sA[warp];

    // Stage this warp's 32 rows: 1 LDG.128 + 1 STS.128 per row (coalesced).
#pragma unroll 8
    for (int r = 0; r < 32; r++) {
        int rr = row0 + r;
        if (rr >= nrows) rr = nrows - 1;
        float4 v = __ldg(reinterpret_cast<const float4*>(Z + (size_t)rr * H) + lane);
        *reinterpret_cast<float4*>(&sa[r][lane * 4]) = v;
    }
    __syncwarp();

    const int qr = lane >> 2;   // 0..7 row within 8-row group
    const int qc = lane & 3;    // 0..3 col within k quad

    float acc[2][16][4];
#pragma unroll
    for (int rt = 0; rt < 2; rt++)
#pragma unroll
        for (int t = 0; t < 16; t++)
#pragma unroll
            for (int c = 0; c < 4; c++) acc[rt][t][c] = 0.f;

    const float4* wf = g_wfrag + (size_t)tb * 16 * 8 * 32 + lane;

#pragma unroll
    for (int s = 0; s < 16; s++) {
        // B fragments for this k-step: 8 float4 = 16 coltiles (MLP batch)
        float4 b[8];
        const float4* wfs = wf + (size_t)s * 8 * 32;
#pragma unroll
        for (int tp = 0; tp < 8; tp++) b[tp] = __ldg(wfs + (size_t)tp * 32);

        // A fragments for both 16-row tiles (conflict-free LDS.32)
        uint32_t a[2][4];
#pragma unroll
        for (int rt = 0; rt < 2; rt++) {
            int rb = rt * 16 + qr;
            a[rt][0] = f2tf32(sa[rb    ][8 * s + qc]);
            a[rt][1] = f2tf32(sa[rb + 8][8 * s + qc]);
            a[rt][2] = f2tf32(sa[rb    ][8 * s + 4 + qc]);
            a[rt][3] = f2tf32(sa[rb + 8][8 * s + 4 + qc]);
        }

#pragma unroll
        for (int tp = 0; tp < 8; tp++) {
            uint32_t b0a = __float_as_uint(b[tp].x);
            uint32_t b1a = __float_as_uint(b[tp].y);
            uint32_t b0b = __float_as_uint(b[tp].z);
            uint32_t b1b = __float_as_uint(b[tp].w);
#pragma unroll
            for (int rt = 0; rt < 2; rt++) {
                MMA_TF32(acc[rt][2 * tp],     a[rt][0], a[rt][1], a[rt][2], a[rt][3], b0a, b1a);
                MMA_TF32(acc[rt][2 * tp + 1], a[rt][0], a[rt][1], a[rt][2], a[rt][3], b0b, b1b);
            }
        }
    }

    // Epilogue: bias (user only) -> fp16 -> warp-private smem (conflict-free
    // half2 STS) -> coalesced LDS.128 + STG.128.
    __syncwarp();
    char* se = reinterpret_cast<char*>(sa);   // row r at byte r*528

#pragma unroll
    for (int t = 0; t < 16; t++) {
        float bx = 0.f, by = 0.f;
        if (is_user) {
            float2 bb = *reinterpret_cast<const float2*>(b1 + 8 * t + 2 * qc);
            bx = bb.x; by = bb.y;
        }
        int cb = (8 * t + 2 * qc) * 2;   // byte offset of half2 in row
#pragma unroll
        for (int rt = 0; rt < 2; rt++) {
            __half2 hlo = __floats2half2_rn(acc[rt][t][0] + bx, acc[rt][t][1] + by);
            __half2 hhi = __floats2half2_rn(acc[rt][t][2] + bx, acc[rt][t][3] + by);
            int rlo = rt * 16 + qr;
            *reinterpret_cast<__half2*>(se + (size_t)rlo * 528 + cb) = hlo;
            *reinterpret_cast<__half2*>(se + (size_t)(rlo + 8) * 528 + cb) = hhi;
        }
    }
    __syncwarp();

    // Write out: 2 rows per instruction, 512 B fully-coalesced.
    const int rl = lane >> 4;          // 0..1
    const int cl = lane & 15;          // 16 B chunk within 256 B row
#pragma unroll
    for (int i = 0; i < 16; i++) {
        int r  = 2 * i + rl;
        int gr = row0 + r;
        uint4 v = *reinterpret_cast<uint4*>(se + (size_t)r * 528 + cl * 16);
        if (gr < nrows)
            *reinterpret_cast<uint4*>(P + (size_t)gr * H + cl * 8) = v;
    }
}

// ---------------------------------------------------------------------------
// Edge kernel: 8 lanes per edge, 8 edges per warp-iteration (2x unroll for
// MLP: 8 gather LDG.128 in flight). Grid-stride.
// ---------------------------------------------------------------------------
__global__ __launch_bounds__(256) void edge_kernel(
    const int* __restrict__ row, const int* __restrict__ col,
    const float* __restrict__ W2, const float* __restrict__ b2,
    float* __restrict__ out, int E)
{
    const int lane = threadIdx.x & 31;
    const int sub  = lane >> 3;   // 0..3
    const int l    = lane & 7;    // lane within edge

    float w2v[16];
#pragma unroll
    for (int i = 0; i < 16; i++) w2v[i] = __ldg(W2 + l * 16 + i);
    const float b2v = __ldg(b2);

    const int warp_global = (int)((blockIdx.x * 256u + threadIdx.x) >> 5);
    const int total_warps = (int)((gridDim.x * 256u) >> 5);

    for (int eb = warp_global * 8; eb < E; eb += total_warps * 8) {
        int e0 = eb + sub;
        int e1 = eb + sub + 4;
        int e0c = (e0 < E) ? e0 : (E - 1);
        int e1c = (e1 < E) ? e1 : (E - 1);

        const int u0 = __ldg(row + e0c);
        const int v0 = __ldg(col + e0c);
        const int u1 = __ldg(row + e1c);
        const int v1 = __ldg(col + e1c);

        const uint4* pu0 = reinterpret_cast<const uint4*>(g_p_user + (size_t)u0 * H) + l * 2;
        const uint4* pi0 = reinterpret_cast<const uint4*>(g_p_item + (size_t)v0 * H) + l * 2;
        const uint4* pu1 = reinterpret_cast<const uint4*>(g_p_user + (size_t)u1 * H) + l * 2;
        const uint4* pi1 = reinterpret_cast<const uint4*>(g_p_item + (size_t)v1 * H) + l * 2;

        uint4 A0 = pu0[0], A1 = pu0[1];
        uint4 C0 = pi0[0], C1 = pi0[1];
        uint4 B0 = pu1[0], B1 = pu1[1];
        uint4 D0 = pi1[0], D1 = pi1[1];

        float s0 = 0.f, s1 = 0.f;
        const __half2* a0 = reinterpret_cast<const __half2*>(&A0);
        const __half2* a1 = reinterpret_cast<const __half2*>(&A1);
        const __half2* c0 = reinterpret_cast<const __half2*>(&C0);
        const __half2* c1 = reinterpret_cast<const __half2*>(&C1);
        const __half2* bb0 = reinterpret_cast<const __half2*>(&B0);
        const __half2* bb1 = reinterpret_cast<const __half2*>(&B1);
        const __half2* d0 = reinterpret_cast<const __half2*>(&D0);
        const __half2* d1 = reinterpret_cast<const __half2*>(&D1);

#pragma unroll
        for (int j = 0; j < 4; j++) {
            float2 fa = __half22float2(a0[j]);
            float2 fb = __half22float2(c0[j]);
            s0 = fmaf(fmaxf(fa.x + fb.x, 0.f), w2v[2 * j],     s0);
            s0 = fmaf(fmaxf(fa.y + fb.y, 0.f), w2v[2 * j + 1], s0);
            float2 ga = __half22float2(bb0[j]);
            float2 gb = __half22float2(d0[j]);
            s1 = fmaf(fmaxf(ga.x + gb.x, 0.f), w2v[2 * j],     s1);
            s1 = fmaf(fmaxf(ga.y + gb.y, 0.f), w2v[2 * j + 1], s1);
        }
#pragma unroll
        for (int j = 0; j < 4; j++) {
            float2 fa = __half22float2(a1[j]);
            float2 fb = __half22float2(c1[j]);
            s0 = fmaf(fmaxf(fa.x + fb.x, 0.f), w2v[8 + 2 * j],     s0);
            s0 = fmaf(fmaxf(fa.y + fb.y, 0.f), w2v[8 + 2 * j + 1], s0);
            float2 ga = __half22float2(bb1[j]);
            float2 gb = __half22float2(d1[j]);
            s1 = fmaf(fmaxf(ga.x + gb.x, 0.f), w2v[8 + 2 * j],     s1);
            s1 = fmaf(fmaxf(ga.y + gb.y, 0.f), w2v[8 + 2 * j + 1], s1);
        }

#pragma unroll
        for (int off = 4; off; off >>= 1) {
            s0 += __shfl_xor_sync(0xFFFFFFFFu, s0, off);
            s1 += __shfl_xor_sync(0xFFFFFFFFu, s1, off);
        }

        if (l == 0) {
            if (e0 < E) out[e0] = s0 + b2v;
            if (e1 < E) out[e1] = s1 + b2v;
        }
    }
}

// ---------------------------------------------------------------------------
// Inputs (metadata order): z_user f32[100000*128], z_item f32[50000*128],
//   row i32[E], col i32[E], W1 f32[256*128], b1 f32[128], W2 f32[128], b2 f32[1]
// Output: f32[E]
// ---------------------------------------------------------------------------
extern "C" void kernel_launch(void* const* d_in, const int* in_sizes, int n_in,
                              void* d_out, int out_size)
{
    const float* z_user = (const float*)d_in[0];
    const float* z_item = (const float*)d_in[1];
    const int*   row    = (const int*)d_in[2];
    const int*   col    = (const int*)d_in[3];
    const float* W1     = (const float*)d_in[4];
    const float* b1     = (const float*)d_in[5];
    const float* W2     = (const float*)d_in[6];
    const float* b2     = (const float*)d_in[7];
    float* out = (float*)d_out;

    const int n_user = in_sizes[0] / H;
    const int n_item = in_sizes[1] / H;
    const int E      = in_sizes[2];

    const int nb_user = (n_user + 63) / 64;
    const int nb_item = (n_item + 63) / 64;

    convert_w<<<32, 256>>>(W1);
    precompute_mma<<<nb_user + nb_item, 64>>>(z_user, z_item, b1,
                                              n_user, n_item, nb_user);
    edge_kernel<<<1184, 256>>>(row, col, W2, b2, out, E);
}

// round 12
// speedup vs baseline: 2.0375x; 1.0909x over previous
#include <cuda_runtime.h>
#include <cuda_fp16.h>
#include <cstdint>

#define H 128
#define N_USER_MAX 100000
#define N_ITEM_MAX 50000

// Precomputed projections stored as fp16 (halves edge gather traffic).
__device__ __half g_p_user[(size_t)N_USER_MAX * H];
__device__ __half g_p_item[(size_t)N_ITEM_MAX * H];

// W1 pre-packed into fp16 m16n8k16 B-fragments.
// Layout [table(2)][kchunk(8)][tpair(8)][lane(32)] uint4 =
//   { b0(coltile 2tp), b1(coltile 2tp), b0(coltile 2tp+1), b1(coltile 2tp+1) }
// For coltile with col base c, lane l: n = c + l/4, k0 = 16*kc + (l%4)*2;
//   b0 = half2(W[k0][n], W[k0+1][n]);  b1 = half2(W[k0+8][n], W[k0+9][n]).
__device__ uint4 g_wfrag16[2 * 8 * 8 * 32];

#define MMA_F16(d, A0, A1, A2, A3, B0, B1)                                   \
    asm volatile(                                                            \
        "mma.sync.aligned.m16n8k16.row.col.f32.f16.f16.f32 "                 \
        "{%0,%1,%2,%3}, {%4,%5,%6,%7}, {%8,%9}, {%0,%1,%2,%3};"              \
        : "+f"(d[0]), "+f"(d[1]), "+f"(d[2]), "+f"(d[3])                     \
        : "r"(A0), "r"(A1), "r"(A2), "r"(A3), "r"(B0), "r"(B1))

__device__ __forceinline__ uint32_t smem_u32(const void* p) {
    uint32_t a;
    asm("{ .reg .u64 t; cvta.to.shared.u64 t, %1; cvt.u32.u64 %0, t; }"
        : "=r"(a) : "l"(p));
    return a;
}

// ---------------------------------------------------------------------------
// convert_w: pack W1 (2H x H fp32) into fp16 B-fragments. 4096 threads.
// ---------------------------------------------------------------------------
__global__ __launch_bounds__(256) void convert_w(const float* __restrict__ W1)
{
    int idx = blockIdx.x * 256 + threadIdx.x;   // 0..4095
    int lane = idx & 31;
    int tp   = (idx >> 5) & 7;
    int kc   = (idx >> 8) & 7;
    int tb   = idx >> 11;

    const float* Wb = W1 + tb * H * H;
    int n0 = 16 * tp + (lane >> 2);
    int n1 = n0 + 8;
    int k0 = 16 * kc + (lane & 3) * 2;

    __half2 b0a = __floats2half2_rn(Wb[(size_t)k0 * H + n0],
                                    Wb[(size_t)(k0 + 1) * H + n0]);
    __half2 b1a = __floats2half2_rn(Wb[(size_t)(k0 + 8) * H + n0],
                                    Wb[(size_t)(k0 + 9) * H + n0]);
    __half2 b0b = __floats2half2_rn(Wb[(size_t)k0 * H + n1],
                                    Wb[(size_t)(k0 + 1) * H + n1]);
    __half2 b1b = __floats2half2_rn(Wb[(size_t)(k0 + 8) * H + n1],
                                    Wb[(size_t)(k0 + 9) * H + n1]);

    uint4 o;
    o.x = *reinterpret_cast<uint32_t*>(&b0a);
    o.y = *reinterpret_cast<uint32_t*>(&b1a);
    o.z = *reinterpret_cast<uint32_t*>(&b0b);
    o.w = *reinterpret_cast<uint32_t*>(&b1b);
    g_wfrag16[idx] = o;
}

// ---------------------------------------------------------------------------
// Precompute via fp16 warp-mma (m16n8k16), fp32 accumulate.
// One warp = 32 rows x 128 cols. Block = 128 threads (4 warps), 128 rows.
// smem: 4 warps x 32 rows x 136 halves = 34.8 KB (static cap OK).
// Row stride 272 B: conflict-free for ldmatrix (8 rows -> banks 4r+c),
// staging STS.64, and epilogue half2 STS. Fully warp-synchronous.
// Per k-chunk (k=16): 8 LDG.128 (B), 2 ldmatrix.x4 (A), 32 mma.
// ---------------------------------------------------------------------------
__global__ __launch_bounds__(128) void precompute_mma(
    const float* __restrict__ z_user, const float* __restrict__ z_item,
    const float* __restrict__ b1,
    int n_user, int n_item, int nb_user)
{
    __shared__ __half sA[4][32][136];

    const int warp = threadIdx.x >> 5;
    const int lane = threadIdx.x & 31;

    const bool is_user = (int)blockIdx.x < nb_user;
    const float* Z;
    __half* P;
    int nrows, tb, blk;
    if (is_user) { Z = z_user; P = g_p_user; nrows = n_user; tb = 0; blk = blockIdx.x; }
    else         { Z = z_item; P = g_p_item; nrows = n_item; tb = 1; blk = blockIdx.x - nb_user; }

    const int row0 = blk * 128 + warp * 32;
    if (row0 >= nrows) return;   // warp-uniform, no block barriers anywhere

    __half (*sa)[136] = sA[warp];

    // Stage 32 rows as fp16: 1 LDG.128 + cvt + 1 STS.64 per row.
#pragma unroll 8
    for (int r = 0; r < 32; r++) {
        int rr = row0 + r;
        if (rr >= nrows) rr = nrows - 1;
        float4 v = __ldg(reinterpret_cast<const float4*>(Z + (size_t)rr * H) + lane);
        __half2 h0 = __floats2half2_rn(v.x, v.y);
        __half2 h1 = __floats2half2_rn(v.z, v.w);
        uint2 pk = { *reinterpret_cast<uint32_t*>(&h0), *reinterpret_cast<uint32_t*>(&h1) };
        *reinterpret_cast<uint2*>(&sa[r][lane * 4]) = pk;
    }
    __syncwarp();

    float acc[2][16][4];
#pragma unroll
    for (int rt = 0; rt < 2; rt++)
#pragma unroll
        for (int t = 0; t < 16; t++)
#pragma unroll
            for (int c = 0; c < 4; c++) acc[rt][t][c] = 0.f;

    // ldmatrix address: matrix q (lane/8), row-in-matrix (lane%8)
    const int q  = lane >> 3;
    const int rq = lane & 7;
    const int lrow = ((q & 1) ? 8 : 0) + rq;   // +8 rows for a1/a3
    const int lcol = (q >> 1) ? 8 : 0;         // +8 k for a2/a3

    const uint4* wf = g_wfrag16 + (size_t)tb * 8 * 8 * 32 + lane;

#pragma unroll
    for (int kc = 0; kc < 8; kc++) {
        // B fragments: 8 uint4 (16 coltiles), batched for MLP
        uint4 b[8];
        const uint4* wfs = wf + (size_t)kc * 8 * 32;
#pragma unroll
        for (int tp = 0; tp < 8; tp++) b[tp] = __ldg(wfs + (size_t)tp * 32);

        // A fragments for both 16-row tiles
        uint32_t a[2][4];
#pragma unroll
        for (int rt = 0; rt < 2; rt++) {
            uint32_t addr = smem_u32(&sa[rt * 16 + lrow][kc * 16 + lcol]);
            asm volatile(
                "ldmatrix.sync.aligned.m8n8.x4.shared.b16 {%0,%1,%2,%3}, [%4];"
                : "=r"(a[rt][0]), "=r"(a[rt][1]), "=r"(a[rt][2]), "=r"(a[rt][3])
                : "r"(addr));
        }

#pragma unroll
        for (int tp = 0; tp < 8; tp++) {
#pragma unroll
            for (int rt = 0; rt < 2; rt++) {
                MMA_F16(acc[rt][2 * tp],     a[rt][0], a[rt][1], a[rt][2], a[rt][3],
                        b[tp].x, b[tp].y);
                MMA_F16(acc[rt][2 * tp + 1], a[rt][0], a[rt][1], a[rt][2], a[rt][3],
                        b[tp].z, b[tp].w);
            }
        }
    }

    // Epilogue: bias (user only, fp32) -> fp16 -> warp-private smem
    // (conflict-free half2 STS) -> coalesced LDS.128 + STG.128.
    __syncwarp();
    char* se = reinterpret_cast<char*>(sa);   // row r at byte r*272
    const int qr = lane >> 2;
    const int qc = lane & 3;

#pragma unroll
    for (int t = 0; t < 16; t++) {
        float bx = 0.f, by = 0.f;
        if (is_user) {
            float2 bb = *reinterpret_cast<const float2*>(b1 + 8 * t + 2 * qc);
            bx = bb.x; by = bb.y;
        }
        int cb = (8 * t + 2 * qc) * 2;   // byte offset of half2 within row
#pragma unroll
        for (int rt = 0; rt < 2; rt++) {
            __half2 hlo = __floats2half2_rn(acc[rt][t][0] + bx, acc[rt][t][1] + by);
            __half2 hhi = __floats2half2_rn(acc[rt][t][2] + bx, acc[rt][t][3] + by);
            int rlo = rt * 16 + qr;
            *reinterpret_cast<__half2*>(se + (size_t)rlo * 272 + cb) = hlo;
            *reinterpret_cast<__half2*>(se + (size_t)(rlo + 8) * 272 + cb) = hhi;
        }
    }
    __syncwarp();

    // Write out: 2 rows per instruction, 512 B coalesced.
    const int rl = lane >> 4;
    const int cl = lane & 15;
#pragma unroll
    for (int i = 0; i < 16; i++) {
        int r  = 2 * i + rl;
        int gr = row0 + r;
        uint4 v = *reinterpret_cast<uint4*>(se + (size_t)r * 272 + cl * 16);
        if (gr < nrows)
            *reinterpret_cast<uint4*>(P + (size_t)gr * H + cl * 8) = v;
    }
}

// ---------------------------------------------------------------------------
// Edge kernel: 8 lanes per edge, 8 edges per warp-iteration. Grid-stride.
//   out[e] = sum_c relu(pu[row[e]][c] + pi[col[e]][c]) * W2[c] + b2
// ---------------------------------------------------------------------------
__global__ __launch_bounds__(256) void edge_kernel(
    const int* __restrict__ row, const int* __restrict__ col,
    const float* __restrict__ W2, const float* __restrict__ b2,
    float* __restrict__ out, int E)
{
    const int lane = threadIdx.x & 31;
    const int sub  = lane >> 3;
    const int l    = lane & 7;

    float w2v[16];
#pragma unroll
    for (int i = 0; i < 16; i++) w2v[i] = __ldg(W2 + l * 16 + i);
    const float b2v = __ldg(b2);

    const int warp_global = (int)((blockIdx.x * 256u + threadIdx.x) >> 5);
    const int total_warps = (int)((gridDim.x * 256u) >> 5);

    for (int eb = warp_global * 8; eb < E; eb += total_warps * 8) {
        int e0 = eb + sub;
        int e1 = eb + sub + 4;
        int e0c = (e0 < E) ? e0 : (E - 1);
        int e1c = (e1 < E) ? e1 : (E - 1);

        const int u0 = __ldg(row + e0c);
        const int v0 = __ldg(col + e0c);
        const int u1 = __ldg(row + e1c);
        const int v1 = __ldg(col + e1c);

        const uint4* pu0 = reinterpret_cast<const uint4*>(g_p_user + (size_t)u0 * H) + l * 2;
        const uint4* pi0 = reinterpret_cast<const uint4*>(g_p_item + (size_t)v0 * H) + l * 2;
        const uint4* pu1 = reinterpret_cast<const uint4*>(g_p_user + (size_t)u1 * H) + l * 2;
        const uint4* pi1 = reinterpret_cast<const uint4*>(g_p_item + (size_t)v1 * H) + l * 2;

        uint4 A0 = pu0[0], A1 = pu0[1];
        uint4 C0 = pi0[0], C1 = pi0[1];
        uint4 B0 = pu1[0], B1 = pu1[1];
        uint4 D0 = pi1[0], D1 = pi1[1];

        float s0 = 0.f, s1 = 0.f;
        const __half2* a0 = reinterpret_cast<const __half2*>(&A0);
        const __half2* a1 = reinterpret_cast<const __half2*>(&A1);
        const __half2* c0 = reinterpret_cast<const __half2*>(&C0);
        const __half2* c1 = reinterpret_cast<const __half2*>(&C1);
        const __half2* bb0 = reinterpret_cast<const __half2*>(&B0);
        const __half2* bb1 = reinterpret_cast<const __half2*>(&B1);
        const __half2* d0 = reinterpret_cast<const __half2*>(&D0);
        const __half2* d1 = reinterpret_cast<const __half2*>(&D1);

#pragma unroll
        for (int j = 0; j < 4; j++) {
            float2 fa = __half22float2(a0[j]);
            float2 fb = __half22float2(c0[j]);
            s0 = fmaf(fmaxf(fa.x + fb.x, 0.f), w2v[2 * j],     s0);
            s0 = fmaf(fmaxf(fa.y + fb.y, 0.f), w2v[2 * j + 1], s0);
            float2 ga = __half22float2(bb0[j]);
            float2 gb = __half22float2(d0[j]);
            s1 = fmaf(fmaxf(ga.x + gb.x, 0.f), w2v[2 * j],     s1);
            s1 = fmaf(fmaxf(ga.y + gb.y, 0.f), w2v[2 * j + 1], s1);
        }
#pragma unroll
        for (int j = 0; j < 4; j++) {
            float2 fa = __half22float2(a1[j]);
            float2 fb = __half22float2(c1[j]);
            s0 = fmaf(fmaxf(fa.x + fb.x, 0.f), w2v[8 + 2 * j],     s0);
            s0 = fmaf(fmaxf(fa.y + fb.y, 0.f), w2v[8 + 2 * j + 1], s0);
            float2 ga = __half22float2(bb1[j]);
            float2 gb = __half22float2(d1[j]);
            s1 = fmaf(fmaxf(ga.x + gb.x, 0.f), w2v[8 + 2 * j],     s1);
            s1 = fmaf(fmaxf(ga.y + gb.y, 0.f), w2v[8 + 2 * j + 1], s1);
        }

#pragma unroll
        for (int off = 4; off; off >>= 1) {
            s0 += __shfl_xor_sync(0xFFFFFFFFu, s0, off);
            s1 += __shfl_xor_sync(0xFFFFFFFFu, s1, off);
        }

        if (l == 0) {
            if (e0 < E) out[e0] = s0 + b2v;
            if (e1 < E) out[e1] = s1 + b2v;
        }
    }
}

// ---------------------------------------------------------------------------
// Inputs (metadata order): z_user f32[100000*128], z_item f32[50000*128],
//   row i32[E], col i32[E], W1 f32[256*128], b1 f32[128], W2 f32[128], b2 f32[1]
// Output: f32[E]
// ---------------------------------------------------------------------------
extern "C" void kernel_launch(void* const* d_in, const int* in_sizes, int n_in,
                              void* d_out, int out_size)
{
    const float* z_user = (const float*)d_in[0];
    const float* z_item = (const float*)d_in[1];
    const int*   row    = (const int*)d_in[2];
    const int*   col    = (const int*)d_in[3];
    const float* W1     = (const float*)d_in[4];
    const float* b1     = (const float*)d_in[5];
    const float* W2     = (const float*)d_in[6];
    const float* b2     = (const float*)d_in[7];
    float* out = (float*)d_out;

    const int n_user = in_sizes[0] / H;
    const int n_item = in_sizes[1] / H;
    const int E      = in_sizes[2];

    const int nb_user = (n_user + 127) / 128;
    const int nb_item = (n_item + 127) / 128;

    convert_w<<<16, 256>>>(W1);
    precompute_mma<<<nb_user + nb_item, 128>>>(z_user, z_item, b1,
                                               n_user, n_item, nb_user);
    edge_kernel<<<1184, 256>>>(row, col, W2, b2, out, E);
}